// round 14
// baseline (speedup 1.0000x reference)
#include <cuda_runtime.h>
#include <cuda_bf16.h>
#include <mma.h>
#include <cstdint>

using namespace nvcuda;

#define B_    16
#define N_    1024
#define M_    1024
#define D_    512
#define NDIAG 2047
#define LOG2E 1.4426950408889634f
#define LN2   0.6931471805599453f
#define NEGW  -1.0e9f

// DP geometry: cluster of 2 CTAs per batch, 16 warps/CTA, 32 rows/warp (R=1).
// Links: 15 intra-CTA smem per CTA + 1 DSMEM (producer-pays remote store).
#define WSTEPS  1055                            // 32 + 1023 steps per warp
#define SB_LEN  1072                            // >= 1055 (max unguarded read index 1054)
#define TH_BYTES (16 * 2048)                    // 16 warps x 2 bufs x 1KB
#define SB_OFF  TH_BYTES                        // 32768
#define FL_OFF  (SB_OFF + 16 * SB_LEN * 4)      // 32768 + 68608 = 101376
#define DYN_SMEM (FL_OFF + 128)                 // 101504 (GEMM needs 36864 <= this)

// ---------------- device scratch ----------------
__device__ __nv_bfloat16 g_zx[(size_t)B_ * N_ * D_];
__device__ __nv_bfloat16 g_zy[(size_t)B_ * M_ * D_];
// theta in bf16, diag-major [b][d][i], pre-scaled by log2e; +128 diag pad for prefetch
__device__ __nv_bfloat16 g_theta_bf[((size_t)B_ * NDIAG + 128) * 1024];
__device__ float g_gpart[B_][16];
__device__ int   g_tprog[B_][15];     // completed GEMM tiles per block-antidiagonal

// ---------------- intrinsics ----------------
__device__ __forceinline__ float ex2f_(float x) {
    float y; asm("ex2.approx.ftz.f32 %0, %1;" : "=f"(y) : "f"(x)); return y;
}
__device__ __forceinline__ float lg2f_(float x) {
    float y; asm("lg2.approx.ftz.f32 %0, %1;" : "=f"(y) : "f"(x)); return y;
}
__device__ __forceinline__ int ld_acq(const int* p) {
    int v; asm volatile("ld.acquire.gpu.b32 %0, [%1];" : "=r"(v) : "l"(p) : "memory"); return v;
}
__device__ __forceinline__ int ld_acq_cta(const int* p) {
    int v; asm volatile("ld.acquire.cta.b32 %0, [%1];" : "=r"(v) : "l"(p) : "memory"); return v;
}
__device__ __forceinline__ void st_rel_cta(int* p, int v) {
    asm volatile("st.release.cta.b32 [%0], %1;" :: "l"(p), "r"(v) : "memory");
}
__device__ __forceinline__ void cpasync16(unsigned int dst, const void* src) {
    asm volatile("cp.async.cg.shared.global [%0], [%1], 16;" :: "r"(dst), "l"(src));
}
// ---- cluster / DSMEM ----
__device__ __forceinline__ unsigned mapa_u32(unsigned laddr, unsigned rank) {
    unsigned r; asm("mapa.shared::cluster.u32 %0, %1, %2;" : "=r"(r) : "r"(laddr), "r"(rank));
    return r;
}
__device__ __forceinline__ void st_dsmem_f32(unsigned addr, float v) {
    asm volatile("st.shared::cluster.f32 [%0], %1;" :: "r"(addr), "f"(v) : "memory");
}
__device__ __forceinline__ void st_rel_cluster(unsigned addr, int v) {
    asm volatile("st.release.cluster.shared::cluster.b32 [%0], %1;" :: "r"(addr), "r"(v) : "memory");
}
__device__ __forceinline__ int ld_acq_cluster(unsigned addr) {
    int v; asm volatile("ld.acquire.cluster.shared::cta.b32 %0, [%1];" : "=r"(v) : "r"(addr) : "memory");
    return v;
}

// soft-max merge of (u+A, g, f+A) in log2 domain, plus theta
__device__ __forceinline__ float cellf(float u, float g, float f,
                                       float A, float A2, float th) {
    float h  = fmaxf(u, f);
    float l  = fminf(u, f);
    float m  = fmaxf(h + A, g);
    float lo = fminf(l + A, g);
    float sum = (u + f) + (A2 + g);
    float mid = (sum - m) - lo;
    float e1 = ex2f_(lo - m);
    float e2 = ex2f_(mid - m);
    float r  = lg2f_((1.0f + e1) + e2);
    return (th + m) + r;
}

// ---------------- 1) fused fp32->bf16 convert + gap partial reduce ----------------
__global__ void __launch_bounds__(512) convgap_kernel(const float* __restrict__ zx,
                                                      const float* __restrict__ zy,
                                                      const float* __restrict__ gw) {
    int blk = blockIdx.x;           // 0..15 (64 rows each)
    int b   = blockIdx.y;
    int c   = threadIdx.x;          // feature 0..511
    if (blk == 0 && b == 0 && c < B_ * 15) ((int*)g_tprog)[c] = 0;

    size_t base = ((size_t)b * N_ + (size_t)blk * 64) * D_ + c;
    const float* px = zx + base;
    const float* py = zy + base;
    __nv_bfloat16* qx = g_zx + base;
    __nv_bfloat16* qy = g_zy + base;
    float sx = 0.f, sy = 0.f;
#pragma unroll 4
    for (int r = 0; r < 64; r++) {
        float vx = px[(size_t)r * D_];
        float vy = py[(size_t)r * D_];
        qx[(size_t)r * D_] = __float2bfloat16(vx);
        qy[(size_t)r * D_] = __float2bfloat16(vy);
        sx += vx; sy += vy;
    }
    float v = sx * (1.0f / N_) * gw[c] + sy * (1.0f / M_) * gw[512 + c];
    __shared__ float red[512];
    red[c] = v;
    __syncthreads();
    for (int st = 256; st > 0; st >>= 1) {
        if (c < st) red[c] += red[c + st];
        __syncthreads();
    }
    if (c == 0) g_gpart[b][blk] = red[0];
}

// ---------------- 2a) GEMM body (512 threads, dynamic smem, antidiag-ordered) ----------------
__device__ void gemm_body(int g, char* smem) {
    int b     = g & 15;
    int arank = g >> 4;             // tile rank in antidiagonal order
    int a = 0, rem = arank;
    while (true) {
        int sz = 8 - (a > 7 ? a - 7 : 7 - a);
        if (rem < sz) break;
        rem -= sz; a++;
    }
    int bi = (a < 8 ? 0 : a - 7) + rem;
    int bj = a - bi;
    int I0 = bi * 128, J0 = bj * 128;

    __nv_bfloat16* smA = (__nv_bfloat16*)smem;       // 128 x 72
    __nv_bfloat16* smB = smA + 128 * 72;

    const __nv_bfloat16* Ag = g_zx + ((size_t)b * N_ + I0) * D_;
    const __nv_bfloat16* Bg = g_zy + ((size_t)b * M_ + J0) * D_;

    int tid = threadIdx.x;
    int warpId = tid >> 5;          // 0..15
    int wr = warpId & 3;            // 4 warp-rows of 32
    int wc = warpId >> 2;           // 4 warp-cols of 32

    wmma::fragment<wmma::accumulator, 16, 16, 16, float> acc[2][2];
#pragma unroll
    for (int i = 0; i < 2; i++)
#pragma unroll
        for (int j = 0; j < 2; j++) wmma::fill_fragment(acc[i][j], 0.0f);

    wmma::fragment<wmma::matrix_a, 16, 16, 16, __nv_bfloat16, wmma::row_major> af[2];
    wmma::fragment<wmma::matrix_b, 16, 16, 16, __nv_bfloat16, wmma::col_major> bfr[2];

    int lr  = tid >> 3;             // 0..63
    int lcq = tid & 7;              // uint4 column

    for (int kc = 0; kc < D_; kc += 64) {
#pragma unroll
        for (int p = 0; p < 2; p++) {
            int row = lr + p * 64;
            *(uint4*)&smA[row * 72 + lcq * 8] =
                *(const uint4*)&Ag[(size_t)row * D_ + kc + lcq * 8];
            *(uint4*)&smB[row * 72 + lcq * 8] =
                *(const uint4*)&Bg[(size_t)row * D_ + kc + lcq * 8];
        }
        __syncthreads();
#pragma unroll
        for (int kk = 0; kk < 64; kk += 16) {
#pragma unroll
            for (int i = 0; i < 2; i++)
                wmma::load_matrix_sync(af[i], &smA[(wr * 32 + i * 16) * 72 + kk], 72);
#pragma unroll
            for (int j = 0; j < 2; j++)
                wmma::load_matrix_sync(bfr[j], &smB[(wc * 32 + j * 16) * 72 + kk], 72);
#pragma unroll
            for (int i = 0; i < 2; i++)
#pragma unroll
                for (int j = 0; j < 2; j++)
                    wmma::mma_sync(acc[i][j], af[i], bfr[j], acc[i][j]);
        }
        __syncthreads();
    }

    // Epilogue: stage 64x128 float halves, drain in anti-diagonal order (bf16, log2e folded).
    float* tile = (float*)smem;
    for (int phase = 0; phase < 2; phase++) {
        if ((wr >> 1) == phase) {
            int lrr = (wr & 1) * 32;
#pragma unroll
            for (int i = 0; i < 2; i++)
#pragma unroll
                for (int j = 0; j < 2; j++)
                    wmma::store_matrix_sync(tile + (size_t)(lrr + i * 16) * 128 + wc * 32 + j * 16,
                                            acc[i][j], 128, wmma::mem_row_major);
        }
        __syncthreads();
        int rowoff = phase * 64;
        for (int e = tid; e < 191 * 64; e += 512) {
            int dl = e >> 6;
            int t  = e & 63;
            int li = (dl > 127 ? dl - 127 : 0) + t;
            int lj = dl - li;
            if (li < 64 && lj >= 0 && lj < 128) {
                int gi = I0 + rowoff + li;
                int gj = J0 + lj;
                g_theta_bf[((size_t)b * NDIAG + (gi + gj)) * 1024 + gi] =
                    __float2bfloat16(tile[li * 128 + lj] * LOG2E);
            }
        }
        __syncthreads();
    }

    __threadfence();                 // every thread: order its theta stores
    __syncthreads();
    if (tid == 0) atomicAdd(&g_tprog[b][a], 1);
}

// ---------------- 2b) DP body: R=1, 16 warps x 32 rows, 2-CTA cluster per batch ----------------
__device__ void dp_body(int b, int half, const float* __restrict__ gb,
                        float* __restrict__ out, char* smem) {
    const int t = threadIdx.x, w = t >> 5, lane = t & 31;
    const int row0w = half * 512 + w * 32;

    float* sBall = (float*)(smem + SB_OFF);
    int*   sF    = (int*)(smem + FL_OFF);
    float* sAp   = (float*)(smem + FL_OFF + 64);

    // theta cp.async: chunk c = local diags 16c..16c+15, 1KB (32 rows x 2B per diag)
    const char* thw = (const char*)g_theta_bf
        + ((size_t)b * NDIAG + (size_t)row0w) * 2048 + (size_t)row0w * 2;
    const unsigned sdstW = (unsigned)__cvta_generic_to_shared(smem) + (unsigned)w * 2048u;

    int tadv = -1;                  // highest GEMM antidiag known complete

#define POLL_THETA(c)                                                         \
    do {                                                                      \
        int dmax_ = row0w + 16 * (c) + 15; if (dmax_ > 2046) dmax_ = 2046;    \
        int amax_ = dmax_ >> 7; if (amax_ > 14) amax_ = 14;                   \
        while (tadv < amax_) {                                                \
            int a_ = tadv + 1;                                                \
            int sz_ = 8 - (a_ > 7 ? a_ - 7 : 7 - a_);                         \
            if (ld_acq(&g_tprog[b][a_]) == sz_) tadv++;                       \
        }                                                                     \
    } while (0)

#define ISSUE_CHUNK(c)                                                        \
    do {                                                                      \
        unsigned db_ = sdstW + (((c) & 1) ? 1024u : 0u);                      \
        _Pragma("unroll")                                                     \
        for (int u2 = 0; u2 < 2; u2++) {                                      \
            int u_ = lane + 32 * u2;                                          \
            cpasync16(db_ + (unsigned)u_ * 16u,                               \
                      thw + (size_t)(16 * (c) + (u_ >> 2)) * 2048 + (u_ & 3) * 16); \
        }                                                                     \
        asm volatile("cp.async.commit_group;");                               \
    } while (0)

    POLL_THETA(0); ISSUE_CHUNK(0);
    POLL_THETA(1); ISSUE_CHUNK(1);

    for (int k = t; k < 16 * SB_LEN; k += 512) sBall[k] = NEGW;
    if (t < 16) sF[t] = -1;
    if (t == 0) {
        float a = 0.f;
#pragma unroll
        for (int k = 0; k < 16; k++) a += g_gpart[b][k];
        *sAp = (a + gb[0]) * LOG2E;
    }
    __syncthreads();
    // both cluster CTAs ready (incoming buffers initialized) before remote stores
    asm volatile("barrier.cluster.arrive.aligned;" ::: "memory");
    asm volatile("barrier.cluster.wait.aligned;" ::: "memory");

    const float A = *sAp, A2 = A + A;

    const bool hasin = (w > 0) || (half == 1);
    const bool ps = (w < 15);                   // produce intra-CTA smem boundary
    const bool pg = (w == 15 && half == 0);     // produce DSMEM boundary to peer CTA
    const int  inslot = (w > 0) ? (w - 1) : 15; // slot 15 = incoming DSMEM buffer

    const float* sIn = sBall + (size_t)inslot * SB_LEN;
    const int*   fIn = &sF[inslot];
    const unsigned fIn32 = (unsigned)__cvta_generic_to_shared(&sF[inslot]);
    float* sOut = sBall + (size_t)((w < 15) ? w : 0) * SB_LEN;
    int*   fOut = &sF[(w < 15) ? w : 0];

    unsigned rIn = 0, rFlag = 0;
    if (pg) {
        rIn   = mapa_u32((unsigned)__cvta_generic_to_shared(&sBall[15 * SB_LEN]), 1u);
        rFlag = mapa_u32((unsigned)__cvta_generic_to_shared(&sF[15]), 1u);
    }

    int scache = -1;
    float pv  = NEGW;                                           // my value at diag p-1
    float nbp = (half == 0 && w == 0 && lane == 0) ? 0.0f : NEGW;  // neighbor at p-2

#define DP_STEP(P, O)                                                        \
    {                                                                        \
        unsigned short ts = *(const unsigned short*)(tbc + (O) * 64 + lane * 2); \
        float bnd = sIn[(P)];                                                \
        float nbr = __shfl_up_sync(0xffffffffu, pv, 1);                      \
        float nb  = (lane == 0) ? bnd : nbr;                                 \
        float th  = __uint_as_float((unsigned)ts << 16);                     \
        float v   = cellf(nb, nbp, pv, A, A2, th);                           \
        v = ((unsigned)((P) - lane) <= 1023u) ? v : NEGW;                    \
        nbp = nb; pv = v;                                                    \
        if (lane == 31) {                                                    \
            int e = (P) - 31;                                                \
            if (ps) {                                                        \
                if ((unsigned)e <= 1023u) sOut[e] = v;                       \
                if (((O) & 3) == 3) st_rel_cta(fOut, e);                     \
            }                                                                \
            if (pg) {                                                        \
                if ((unsigned)e <= 1023u) st_dsmem_f32(rIn + 4u * (unsigned)e, v); \
                if (((O) & 3) == 3) st_rel_cluster(rFlag, e);                \
            }                                                                \
        }                                                                    \
    }

    int p = 0;
    for (int c = 0; c < 65; c++) {             // 65 full chunks: steps 0..1039
        asm volatile("cp.async.wait_group 1;");
        __syncwarp();
        const char* tbc = smem + w * 2048 + (c & 1) * 1024;
#pragma unroll
        for (int blk = 0; blk < 2; blk++) {
            if (hasin) {
                int tgt = min(p + 7, 1023);
                if (w == 0) { while (scache < tgt) scache = ld_acq_cluster(fIn32); }
                else        { while (scache < tgt) scache = ld_acq_cta(fIn); }
            }
#pragma unroll
            for (int k = 0; k < 8; k++) {
                DP_STEP(p, (blk * 8 + k))
                p++;
            }
        }
        POLL_THETA(c + 2);
        ISSUE_CHUNK(c + 2);
    }
    // tail chunk 65: steps 1040..1054 (15 steps)
    {
        asm volatile("cp.async.wait_group 1;");
        __syncwarp();
        const char* tbc = smem + w * 2048 + (65 & 1) * 1024;
        if (hasin) {
            if (w == 0) { while (scache < 1023) scache = ld_acq_cluster(fIn32); }
            else        { while (scache < 1023) scache = ld_acq_cta(fIn); }
        }
#pragma unroll
        for (int k = 0; k < 8; k++) { DP_STEP(p, k) p++; }
#pragma unroll
        for (int k = 8; k < 15; k++) { DP_STEP(p, k) p++; }
    }
#undef DP_STEP
#undef ISSUE_CHUNK
#undef POLL_THETA

    if (ps && lane == 31) st_rel_cta(fOut, 4096);
    if (pg && lane == 31) st_rel_cluster(rFlag, 4096);

    // half 1, warp 15, lane 31 = global row 1023 at diag 2046 -> V[N][M]
    if (half == 1 && w == 15 && lane == 31) out[b] = pv * LN2;
}

// ---------------- 2) fused kernel: 32 DP CTAs (16 clusters) + 1024 GEMM CTAs ----------------
__global__ void __launch_bounds__(512) __cluster_dims__(2, 1, 1)
fused_kernel(const float* __restrict__ gb, float* __restrict__ out) {
    extern __shared__ char smem_dyn[];
    if (blockIdx.x < 2 * B_) dp_body(blockIdx.x >> 1, blockIdx.x & 1, gb, out, smem_dyn);
    else                     gemm_body(blockIdx.x - 2 * B_, smem_dyn);
}

// ---------------- launch ----------------
extern "C" void kernel_launch(void* const* d_in, const int* in_sizes, int n_in,
                              void* d_out, int out_size) {
    (void)in_sizes; (void)n_in; (void)out_size;
    const float* zx = (const float*)d_in[0];
    const float* zy = (const float*)d_in[1];
    const float* gw = (const float*)d_in[2];
    const float* gb = (const float*)d_in[3];
    float* out = (float*)d_out;

    cudaFuncSetAttribute(fused_kernel, cudaFuncAttributeMaxDynamicSharedMemorySize, DYN_SMEM);

    convgap_kernel<<<dim3(16, B_), 512>>>(zx, zy, gw);
    fused_kernel<<<2 * B_ + 1024, 512, DYN_SMEM>>>(gb, out);
}

// round 15
// speedup vs baseline: 1.2167x; 1.2167x over previous
#include <cuda_runtime.h>
#include <cuda_bf16.h>
#include <mma.h>
#include <cstdint>

using namespace nvcuda;

#define B_    16
#define N_    1024
#define M_    1024
#define D_    512
#define NDIAG 2047
#define LOG2E 1.4426950408889634f
#define LN2   0.6931471805599453f
#define NEGW  -1.0e9f
#define SENT  0xff800000u                       // -inf: provably never a computed value

// DP geometry: cluster of 2 CTAs per batch, 16 warps/CTA, 32 rows/warp (R=1).
// Links: 15 intra-CTA smem + 1 DSMEM, all via data-as-flag sentinel handshake.
#define SB_LEN  1072                            // >= 1055 (max unguarded read index 1054)
#define TH_BYTES (16 * 2048)                    // 16 warps x 2 bufs x 1KB
#define SB_OFF  TH_BYTES                        // 32768
#define AP_OFF  (SB_OFF + 16 * SB_LEN * 4)      // 32768 + 68608 = 101376
#define DYN_SMEM (AP_OFF + 128)                 // 101504 (GEMM needs 36864 <= this)

// ---------------- device scratch ----------------
__device__ __nv_bfloat16 g_zx[(size_t)B_ * N_ * D_];
__device__ __nv_bfloat16 g_zy[(size_t)B_ * M_ * D_];
// theta in bf16, diag-major [b][d][i], pre-scaled by log2e; +128 diag pad for prefetch
__device__ __nv_bfloat16 g_theta_bf[((size_t)B_ * NDIAG + 128) * 1024];
__device__ float g_gpart[B_][16];
__device__ int   g_tprog[B_][15];     // completed GEMM tiles per block-antidiagonal

// ---------------- intrinsics ----------------
__device__ __forceinline__ float ex2f_(float x) {
    float y; asm("ex2.approx.ftz.f32 %0, %1;" : "=f"(y) : "f"(x)); return y;
}
__device__ __forceinline__ float lg2f_(float x) {
    float y; asm("lg2.approx.ftz.f32 %0, %1;" : "=f"(y) : "f"(x)); return y;
}
__device__ __forceinline__ int ld_acq(const int* p) {
    int v; asm volatile("ld.acquire.gpu.b32 %0, [%1];" : "=r"(v) : "l"(p) : "memory"); return v;
}
__device__ __forceinline__ void cpasync16(unsigned int dst, const void* src) {
    asm volatile("cp.async.cg.shared.global [%0], [%1], 16;" :: "r"(dst), "l"(src));
}
// ---- sentinel link ops (relaxed, cluster scope covers both intra and cross CTA) ----
__device__ __forceinline__ unsigned ld_slot(unsigned addr) {
    unsigned v;
    asm volatile("ld.relaxed.cluster.shared::cta.b32 %0, [%1];" : "=r"(v) : "r"(addr) : "memory");
    return v;
}
__device__ __forceinline__ void st_slot(unsigned addr, float v) {
    asm volatile("st.relaxed.cta.shared::cta.f32 [%0], %1;" :: "r"(addr), "f"(v) : "memory");
}
__device__ __forceinline__ void st_slot_remote(unsigned addr, float v) {
    asm volatile("st.relaxed.cluster.shared::cluster.f32 [%0], %1;" :: "r"(addr), "f"(v) : "memory");
}
__device__ __forceinline__ unsigned mapa_u32(unsigned laddr, unsigned rank) {
    unsigned r; asm("mapa.shared::cluster.u32 %0, %1, %2;" : "=r"(r) : "r"(laddr), "r"(rank));
    return r;
}

// soft-max merge of (u+A, g, f+A) in log2 domain, plus theta
__device__ __forceinline__ float cellf(float u, float g, float f,
                                       float A, float A2, float th) {
    float h  = fmaxf(u, f);
    float l  = fminf(u, f);
    float m  = fmaxf(h + A, g);
    float lo = fminf(l + A, g);
    float sum = (u + f) + (A2 + g);
    float mid = (sum - m) - lo;
    float e1 = ex2f_(lo - m);
    float e2 = ex2f_(mid - m);
    float r  = lg2f_((1.0f + e1) + e2);
    return (th + m) + r;
}

// ---------------- 1) fused fp32->bf16 convert + gap partial reduce ----------------
__global__ void __launch_bounds__(512) convgap_kernel(const float* __restrict__ zx,
                                                      const float* __restrict__ zy,
                                                      const float* __restrict__ gw) {
    int blk = blockIdx.x;           // 0..15 (64 rows each)
    int b   = blockIdx.y;
    int c   = threadIdx.x;          // feature 0..511
    if (blk == 0 && b == 0 && c < B_ * 15) ((int*)g_tprog)[c] = 0;

    size_t base = ((size_t)b * N_ + (size_t)blk * 64) * D_ + c;
    const float* px = zx + base;
    const float* py = zy + base;
    __nv_bfloat16* qx = g_zx + base;
    __nv_bfloat16* qy = g_zy + base;
    float sx = 0.f, sy = 0.f;
#pragma unroll 4
    for (int r = 0; r < 64; r++) {
        float vx = px[(size_t)r * D_];
        float vy = py[(size_t)r * D_];
        qx[(size_t)r * D_] = __float2bfloat16(vx);
        qy[(size_t)r * D_] = __float2bfloat16(vy);
        sx += vx; sy += vy;
    }
    float v = sx * (1.0f / N_) * gw[c] + sy * (1.0f / M_) * gw[512 + c];
    __shared__ float red[512];
    red[c] = v;
    __syncthreads();
    for (int st = 256; st > 0; st >>= 1) {
        if (c < st) red[c] += red[c + st];
        __syncthreads();
    }
    if (c == 0) g_gpart[b][blk] = red[0];
}

// ---------------- 2a) GEMM body (512 threads, dynamic smem, antidiag-ordered) ----------------
__device__ void gemm_body(int g, char* smem) {
    int b     = g & 15;
    int arank = g >> 4;             // tile rank in antidiagonal order
    int a = 0, rem = arank;
    while (true) {
        int sz = 8 - (a > 7 ? a - 7 : 7 - a);
        if (rem < sz) break;
        rem -= sz; a++;
    }
    int bi = (a < 8 ? 0 : a - 7) + rem;
    int bj = a - bi;
    int I0 = bi * 128, J0 = bj * 128;

    __nv_bfloat16* smA = (__nv_bfloat16*)smem;       // 128 x 72
    __nv_bfloat16* smB = smA + 128 * 72;

    const __nv_bfloat16* Ag = g_zx + ((size_t)b * N_ + I0) * D_;
    const __nv_bfloat16* Bg = g_zy + ((size_t)b * M_ + J0) * D_;

    int tid = threadIdx.x;
    int warpId = tid >> 5;          // 0..15
    int wr = warpId & 3;            // 4 warp-rows of 32
    int wc = warpId >> 2;           // 4 warp-cols of 32

    wmma::fragment<wmma::accumulator, 16, 16, 16, float> acc[2][2];
#pragma unroll
    for (int i = 0; i < 2; i++)
#pragma unroll
        for (int j = 0; j < 2; j++) wmma::fill_fragment(acc[i][j], 0.0f);

    wmma::fragment<wmma::matrix_a, 16, 16, 16, __nv_bfloat16, wmma::row_major> af[2];
    wmma::fragment<wmma::matrix_b, 16, 16, 16, __nv_bfloat16, wmma::col_major> bfr[2];

    int lr  = tid >> 3;             // 0..63
    int lcq = tid & 7;              // uint4 column

    for (int kc = 0; kc < D_; kc += 64) {
#pragma unroll
        for (int p = 0; p < 2; p++) {
            int row = lr + p * 64;
            *(uint4*)&smA[row * 72 + lcq * 8] =
                *(const uint4*)&Ag[(size_t)row * D_ + kc + lcq * 8];
            *(uint4*)&smB[row * 72 + lcq * 8] =
                *(const uint4*)&Bg[(size_t)row * D_ + kc + lcq * 8];
        }
        __syncthreads();
#pragma unroll
        for (int kk = 0; kk < 64; kk += 16) {
#pragma unroll
            for (int i = 0; i < 2; i++)
                wmma::load_matrix_sync(af[i], &smA[(wr * 32 + i * 16) * 72 + kk], 72);
#pragma unroll
            for (int j = 0; j < 2; j++)
                wmma::load_matrix_sync(bfr[j], &smB[(wc * 32 + j * 16) * 72 + kk], 72);
#pragma unroll
            for (int i = 0; i < 2; i++)
#pragma unroll
                for (int j = 0; j < 2; j++)
                    wmma::mma_sync(acc[i][j], af[i], bfr[j], acc[i][j]);
        }
        __syncthreads();
    }

    // Epilogue: stage 64x128 float halves, drain in anti-diagonal order (bf16, log2e folded).
    float* tile = (float*)smem;
    for (int phase = 0; phase < 2; phase++) {
        if ((wr >> 1) == phase) {
            int lrr = (wr & 1) * 32;
#pragma unroll
            for (int i = 0; i < 2; i++)
#pragma unroll
                for (int j = 0; j < 2; j++)
                    wmma::store_matrix_sync(tile + (size_t)(lrr + i * 16) * 128 + wc * 32 + j * 16,
                                            acc[i][j], 128, wmma::mem_row_major);
        }
        __syncthreads();
        int rowoff = phase * 64;
        for (int e = tid; e < 191 * 64; e += 512) {
            int dl = e >> 6;
            int t  = e & 63;
            int li = (dl > 127 ? dl - 127 : 0) + t;
            int lj = dl - li;
            if (li < 64 && lj >= 0 && lj < 128) {
                int gi = I0 + rowoff + li;
                int gj = J0 + lj;
                g_theta_bf[((size_t)b * NDIAG + (gi + gj)) * 1024 + gi] =
                    __float2bfloat16(tile[li * 128 + lj] * LOG2E);
            }
        }
        __syncthreads();
    }

    __threadfence();                 // every thread: order its theta stores
    __syncthreads();
    if (tid == 0) atomicAdd(&g_tprog[b][a], 1);
}

// ---------------- 2b) DP body: R=1, 16 warps x 32 rows, 2-CTA cluster per batch ----------------
__device__ void dp_body(int b, int half, const float* __restrict__ gb,
                        float* __restrict__ out, char* smem) {
    const int t = threadIdx.x, w = t >> 5, lane = t & 31;
    const int row0w = half * 512 + w * 32;

    float* sBall = (float*)(smem + SB_OFF);
    float* sAp   = (float*)(smem + AP_OFF);

    // theta cp.async: chunk c = local diags 16c..16c+15, 1KB (32 rows x 2B per diag)
    const char* thw = (const char*)g_theta_bf
        + ((size_t)b * NDIAG + (size_t)row0w) * 2048 + (size_t)row0w * 2;
    const unsigned sdstW = (unsigned)__cvta_generic_to_shared(smem) + (unsigned)w * 2048u;

    int tadv = -1;                  // highest GEMM antidiag known complete

#define POLL_THETA(c)                                                         \
    do {                                                                      \
        int dmax_ = row0w + 16 * (c) + 15; if (dmax_ > 2046) dmax_ = 2046;    \
        int amax_ = dmax_ >> 7; if (amax_ > 14) amax_ = 14;                   \
        while (tadv < amax_) {                                                \
            int a_ = tadv + 1;                                                \
            int sz_ = 8 - (a_ > 7 ? a_ - 7 : 7 - a_);                         \
            if (ld_acq(&g_tprog[b][a_]) == sz_) tadv++;                       \
        }                                                                     \
    } while (0)

#define ISSUE_CHUNK(c)                                                        \
    do {                                                                      \
        unsigned db_ = sdstW + (((c) & 1) ? 1024u : 0u);                      \
        _Pragma("unroll")                                                     \
        for (int u2 = 0; u2 < 2; u2++) {                                      \
            int u_ = lane + 32 * u2;                                          \
            cpasync16(db_ + (unsigned)u_ * 16u,                               \
                      thw + (size_t)(16 * (c) + (u_ >> 2)) * 2048 + (u_ & 3) * 16); \
        }                                                                     \
        asm volatile("cp.async.commit_group;");                               \
    } while (0)

    POLL_THETA(0); ISSUE_CHUNK(0);
    POLL_THETA(1); ISSUE_CHUNK(1);

    // Init boundary buffers: writable slots [0,1024) get SENTINEL; the rest (never
    // written: idx >= 1024, and CTA0's incoming slot 15) get NEGW so no spin hangs.
    for (int k = t; k < 16 * SB_LEN; k += 512) {
        int slot = k / SB_LEN;
        int idx  = k - slot * SB_LEN;
        bool writable = (idx < 1024) && (slot < 15 || half == 1);
        ((unsigned*)sBall)[k] = writable ? SENT : __float_as_uint(NEGW);
    }
    if (t == 0) {
        float a = 0.f;
#pragma unroll
        for (int k = 0; k < 16; k++) a += g_gpart[b][k];
        *sAp = (a + gb[0]) * LOG2E;
    }
    __syncthreads();
    // both cluster CTAs ready (incoming buffers initialized) before remote stores
    asm volatile("barrier.cluster.arrive.aligned;" ::: "memory");
    asm volatile("barrier.cluster.wait.aligned;" ::: "memory");

    const float A = *sAp, A2 = A + A;

    const bool ps = (w < 15);                   // produce intra-CTA smem boundary
    const bool pg = (w == 15 && half == 0);     // produce DSMEM boundary to peer CTA
    const int  inslot = (w > 0) ? (w - 1) : 15; // slot 15 = incoming DSMEM buffer

    const unsigned sInA  = (unsigned)__cvta_generic_to_shared(sBall + (size_t)inslot * SB_LEN);
    const unsigned sOutA = (unsigned)__cvta_generic_to_shared(sBall + (size_t)((w < 15) ? w : 0) * SB_LEN);

    unsigned rIn = 0;
    if (pg) rIn = mapa_u32((unsigned)__cvta_generic_to_shared(&sBall[15 * SB_LEN]), 1u);

    float pv  = NEGW;                                           // my value at diag p-1
    float nbp = (half == 0 && w == 0 && lane == 0) ? 0.0f : NEGW;  // neighbor at p-2

#define DP_STEP(P, O)                                                        \
    {                                                                        \
        unsigned short ts = *(const unsigned short*)(tbc + (O) * 64 + lane * 2); \
        unsigned bb = ld_slot(sInA + 4u * (unsigned)(P));                    \
        while (bb == SENT) bb = ld_slot(sInA + 4u * (unsigned)(P));          \
        float bnd = __uint_as_float(bb);                                     \
        float nbr = __shfl_up_sync(0xffffffffu, pv, 1);                      \
        float nb  = (lane == 0) ? bnd : nbr;                                 \
        float th  = __uint_as_float((unsigned)ts << 16);                     \
        float v   = cellf(nb, nbp, pv, A, A2, th);                           \
        v = ((unsigned)((P) - lane) <= 1023u) ? v : NEGW;                    \
        nbp = nb; pv = v;                                                    \
        if (lane == 31) {                                                    \
            int e = (P) - 31;                                                \
            if (ps && (unsigned)e <= 1023u) st_slot(sOutA + 4u * (unsigned)e, v); \
            if (pg && (unsigned)e <= 1023u) st_slot_remote(rIn + 4u * (unsigned)e, v); \
        }                                                                    \
    }

    int p = 0;
    for (int c = 0; c < 65; c++) {             // 65 full chunks: steps 0..1039
        asm volatile("cp.async.wait_group 1;");
        __syncwarp();
        const char* tbc = smem + w * 2048 + (c & 1) * 1024;
#pragma unroll
        for (int k = 0; k < 16; k++) {
            DP_STEP(p, k)
            p++;
        }
        POLL_THETA(c + 2);
        ISSUE_CHUNK(c + 2);
    }
    // tail chunk 65: steps 1040..1054 (15 steps)
    {
        asm volatile("cp.async.wait_group 1;");
        __syncwarp();
        const char* tbc = smem + w * 2048 + (65 & 1) * 1024;
#pragma unroll
        for (int k = 0; k < 15; k++) { DP_STEP(p, k) p++; }
    }
#undef DP_STEP
#undef ISSUE_CHUNK
#undef POLL_THETA

    // half 1, warp 15, lane 31 = global row 1023 at diag 2046 -> V[N][M]
    if (half == 1 && w == 15 && lane == 31) out[b] = pv * LN2;
}

// ---------------- 2) fused kernel: 32 DP CTAs (16 clusters) + 1024 GEMM CTAs ----------------
__global__ void __launch_bounds__(512) __cluster_dims__(2, 1, 1)
fused_kernel(const float* __restrict__ gb, float* __restrict__ out) {
    extern __shared__ char smem_dyn[];
    if (blockIdx.x < 2 * B_) dp_body(blockIdx.x >> 1, blockIdx.x & 1, gb, out, smem_dyn);
    else                     gemm_body(blockIdx.x - 2 * B_, smem_dyn);
}

// ---------------- launch ----------------
extern "C" void kernel_launch(void* const* d_in, const int* in_sizes, int n_in,
                              void* d_out, int out_size) {
    (void)in_sizes; (void)n_in; (void)out_size;
    const float* zx = (const float*)d_in[0];
    const float* zy = (const float*)d_in[1];
    const float* gw = (const float*)d_in[2];
    const float* gb = (const float*)d_in[3];
    float* out = (float*)d_out;

    cudaFuncSetAttribute(fused_kernel, cudaFuncAttributeMaxDynamicSharedMemorySize, DYN_SMEM);

    convgap_kernel<<<dim3(16, B_), 512>>>(zx, zy, gw);
    fused_kernel<<<2 * B_ + 1024, 512, DYN_SMEM>>>(gb, out);
}